// round 1
// baseline (speedup 1.0000x reference)
#include <cuda_runtime.h>
#include <cuda_bf16.h>

#define BATCH   16384
#define EMBED   64
#define N_EDGES 524288
#define EPW     32   // edges per warp in the aggregation kernel

// Scratch (device globals — no allocation allowed)
__device__ float g_acc[BATCH * EMBED];   // 4 MB segment sums
__device__ float g_cnt[BATCH];           // segment counts

// ---------------------------------------------------------------------------
// Kernel 1: zero the accumulators (graph replays re-run this every launch)
// ---------------------------------------------------------------------------
__global__ void zero_kernel() {
    const int stride = gridDim.x * blockDim.x;
    int i = blockIdx.x * blockDim.x + threadIdx.x;
    for (int idx = i; idx < BATCH * EMBED; idx += stride) g_acc[idx] = 0.0f;
    for (int idx = i; idx < BATCH;         idx += stride) g_cnt[idx] = 0.0f;
}

// ---------------------------------------------------------------------------
// Kernel 2: edge aggregation. One warp owns EPW consecutive edges.
// seg_ids is sorted, so consecutive edges usually share a segment:
// accumulate in registers, flush with atomics only when the segment changes
// (~32x fewer atomics than per-edge).
// Each lane holds 2 of the 64 dims (float2) -> one coalesced 256B row load.
// ---------------------------------------------------------------------------
__global__ void agg_kernel(const int*   __restrict__ neigh_ids,
                           const int*   __restrict__ seg_ids,
                           const float* __restrict__ features) {
    const int warp = (blockIdx.x * blockDim.x + threadIdx.x) >> 5;
    const int lane = threadIdx.x & 31;
    const int e0 = warp * EPW;
    if (e0 >= N_EDGES) return;
    const int e1 = min(e0 + EPW, N_EDGES);

    const float2* __restrict__ feats2 = (const float2*)features;

    // software pipeline: prefetch edge e+1's ids and feature row while
    // accumulating edge e (MLP >= 2 on the DRAM-latency chain)
    int   s_next = seg_ids[e0];
    int   n_next = neigh_ids[e0];
    float2 v_next = feats2[(size_t)n_next * 32 + lane];

    float2 acc = make_float2(0.0f, 0.0f);
    int cur = s_next;
    int runlen = 0;

    for (int e = e0; e < e1; ++e) {
        const int s = s_next;
        const float2 v = v_next;
        if (e + 1 < e1) {
            s_next = seg_ids[e + 1];
            n_next = neigh_ids[e + 1];
            v_next = feats2[(size_t)n_next * 32 + lane];
        }
        if (s != cur) {
            atomicAdd(&g_acc[cur * EMBED + 2 * lane],     acc.x);
            atomicAdd(&g_acc[cur * EMBED + 2 * lane + 1], acc.y);
            if (lane == 0) atomicAdd(&g_cnt[cur], (float)runlen);
            acc = make_float2(0.0f, 0.0f);
            cur = s;
            runlen = 0;
        }
        acc.x += v.x;
        acc.y += v.y;
        ++runlen;
    }
    atomicAdd(&g_acc[cur * EMBED + 2 * lane],     acc.x);
    atomicAdd(&g_acc[cur * EMBED + 2 * lane + 1], acc.y);
    if (lane == 0) atomicAdd(&g_cnt[cur], (float)runlen);
}

// ---------------------------------------------------------------------------
// Kernel 3: self gather + mean + [self|neigh] @ w1^T + b1, relu.
// w1 (64x128) held in smem TRANSPOSED (w1t[k][j], j contiguous over lanes ->
// conflict-free). 256 threads = 4 rows x 64 output dims per iteration.
// Small grid so each block loads w1 once and loops over many row groups.
// ---------------------------------------------------------------------------
__global__ void mlp_kernel(const int*   __restrict__ nodes,
                           const float* __restrict__ features,
                           const float* __restrict__ w1,
                           const float* __restrict__ b1,
                           float*       __restrict__ out) {
    __shared__ float w1t[128][64];   // [k][j]  (32 KB)
    __shared__ float b1s[64];
    __shared__ float comb[4][128];   // 4 rows of concat(self, neigh_mean)

    for (int idx = threadIdx.x; idx < 64 * 128; idx += blockDim.x) {
        const int j = idx >> 7;      // output dim
        const int k = idx & 127;     // input dim
        w1t[k][j] = w1[idx];         // w1 is row-major (64,128)
    }
    if (threadIdx.x < 64) b1s[threadIdx.x] = b1[threadIdx.x];
    __syncthreads();

    const int r = threadIdx.x >> 6;  // row within group (0..3)
    const int j = threadIdx.x & 63;  // output dim

    for (int base = blockIdx.x * 4; base < BATCH; base += gridDim.x * 4) {
        const int b = base + r;
        const int node = nodes[b];
        comb[r][j] = features[(size_t)node * EMBED + j];
        const float cnt = fmaxf(g_cnt[b], 1.0f);
        comb[r][64 + j] = g_acc[b * EMBED + j] * (1.0f / cnt);
        __syncthreads();

        float s = b1s[j];
        #pragma unroll
        for (int k = 0; k < 128; ++k)
            s = fmaf(comb[r][k], w1t[k][j], s);
        out[(size_t)b * EMBED + j] = fmaxf(s, 0.0f);
        __syncthreads();
    }
}

// ---------------------------------------------------------------------------
// Launch
// inputs (metadata order): nodes(i32,16384) neigh_ids(i32,524288)
// seg_ids(i32,524288) features(f32,64M) w1(f32,8192) b1(f32,64)
// output: f32 (16384, 64)
// ---------------------------------------------------------------------------
extern "C" void kernel_launch(void* const* d_in, const int* in_sizes, int n_in,
                              void* d_out, int out_size) {
    const int*   nodes     = (const int*)  d_in[0];
    const int*   neigh_ids = (const int*)  d_in[1];
    const int*   seg_ids   = (const int*)  d_in[2];
    const float* features  = (const float*)d_in[3];
    const float* w1        = (const float*)d_in[4];
    const float* b1        = (const float*)d_in[5];
    float*       out       = (float*)d_out;

    zero_kernel<<<1024, 256>>>();

    const int n_warps  = N_EDGES / EPW;           // 16384 warps
    const int n_blocks = n_warps / 8;             // 256 thr = 8 warps/block
    agg_kernel<<<n_blocks, 256>>>(neigh_ids, seg_ids, features);

    mlp_kernel<<<592, 256>>>(nodes, features, w1, b1, out);
}

// round 2
// speedup vs baseline: 1.7144x; 1.7144x over previous
#include <cuda_runtime.h>
#include <cuda_bf16.h>

#define BATCH   16384
#define EMBED   64
#define N_EDGES 524288
#define FULL    0xffffffffu

// Scratch (device globals — no allocation allowed)
__device__ float g_acc[BATCH * EMBED];   // 4 MB segment sums
__device__ float g_cnt[BATCH];           // segment counts

// ---------------------------------------------------------------------------
// Kernel 1: vectorized zero (graph replays re-run this every launch)
// g_acc: 1048576 floats = 262144 float4;  g_cnt: 16384 floats = 4096 float4
// ---------------------------------------------------------------------------
__global__ void zero_kernel() {
    const int i = blockIdx.x * blockDim.x + threadIdx.x;
    float4 z = make_float4(0.f, 0.f, 0.f, 0.f);
    if (i < 262144) {
        ((float4*)g_acc)[i] = z;
    } else if (i < 262144 + 4096) {
        ((float4*)g_cnt)[i - 262144] = z;
    }
}

// ---------------------------------------------------------------------------
// Kernel 2: edge aggregation. One warp owns 32 consecutive edges.
// ids loaded lane-parallel (coalesced), broadcast via shfl.
// Feature rows fetched in batches of 8 independent loads -> MLP=8/warp.
// seg_ids sorted: register-accumulate per run, atomic flush on change only.
// ---------------------------------------------------------------------------
__global__ void agg_kernel(const int*   __restrict__ neigh_ids,
                           const int*   __restrict__ seg_ids,
                           const float* __restrict__ features) {
    const int warp = (blockIdx.x * blockDim.x + threadIdx.x) >> 5;
    const int lane = threadIdx.x & 31;
    const int e0 = warp * 32;
    if (e0 >= N_EDGES) return;

    // coalesced: lane l owns ids of edge e0+l
    const int my_seg = seg_ids[e0 + lane];
    const int my_nid = neigh_ids[e0 + lane];

    const float2* __restrict__ feats2 = (const float2*)features;

    float2 acc = make_float2(0.0f, 0.0f);
    int cur = __shfl_sync(FULL, my_seg, 0);
    int runlen = 0;

    #pragma unroll
    for (int c = 0; c < 32; c += 8) {
        int   n[8], s[8];
        float2 v[8];
        #pragma unroll
        for (int u = 0; u < 8; ++u) n[u] = __shfl_sync(FULL, my_nid, c + u);
        // 8 independent 256B row loads in flight
        #pragma unroll
        for (int u = 0; u < 8; ++u) v[u] = feats2[(size_t)n[u] * 32 + lane];
        #pragma unroll
        for (int u = 0; u < 8; ++u) s[u] = __shfl_sync(FULL, my_seg, c + u);
        #pragma unroll
        for (int u = 0; u < 8; ++u) {
            if (s[u] != cur) {            // warp-uniform branch (s is broadcast)
                atomicAdd(&g_acc[cur * EMBED + 2 * lane],     acc.x);
                atomicAdd(&g_acc[cur * EMBED + 2 * lane + 1], acc.y);
                if (lane == 0) atomicAdd(&g_cnt[cur], (float)runlen);
                acc = make_float2(0.0f, 0.0f);
                cur = s[u];
                runlen = 0;
            }
            acc.x += v[u].x;
            acc.y += v[u].y;
            ++runlen;
        }
    }
    atomicAdd(&g_acc[cur * EMBED + 2 * lane],     acc.x);
    atomicAdd(&g_acc[cur * EMBED + 2 * lane + 1], acc.y);
    if (lane == 0) atomicAdd(&g_cnt[cur], (float)runlen);
}

// ---------------------------------------------------------------------------
// Kernel 3: self gather + mean + [self|neigh] @ w1^T + b1, relu.
// Register-tiled weights: 256 threads = 4 k-groups (warp-uniform g = tid>>6)
// x 64 output dims. Each thread holds 32 w1 values in registers (loaded once
// per block from stride-129-padded smem -> conflict-free). Inner loop reads
// comb via float4 *broadcast* LDS only. 4 partials per (row,j) reduced via
// stride-5-padded smem.
// ---------------------------------------------------------------------------
__global__ void mlp_kernel(const int*   __restrict__ nodes,
                           const float* __restrict__ features,
                           const float* __restrict__ w1,
                           const float* __restrict__ b1,
                           float*       __restrict__ out) {
    __shared__ float w1s[64 * 129];       // staged w1, row stride 129 (pad)
    __shared__ float b1s[64];
    __shared__ float comb[4][128];        // 4 rows of concat(self, neigh_mean)
    __shared__ float part[4][64 * 5];     // partials, stride-5 pad over g

    // stage w1 (row-major [64][128]) coalesced into padded smem
    for (int idx = threadIdx.x; idx < 64 * 128; idx += blockDim.x) {
        const int j = idx >> 7;
        const int k = idx & 127;
        w1s[j * 129 + k] = w1[idx];
    }
    if (threadIdx.x < 64) b1s[threadIdx.x] = b1[threadIdx.x];
    __syncthreads();

    const int g = threadIdx.x >> 6;       // k-group 0..3 (warp-uniform)
    const int j = threadIdx.x & 63;       // output dim

    // per-thread weight registers: w1[j][g*32 .. g*32+31]
    // smem addr = j*129 + g*32 + kk; within a warp j is consecutive ->
    // bank = (j + kk) mod 32 -> conflict-free.
    float w[32];
    #pragma unroll
    for (int kk = 0; kk < 32; ++kk) w[kk] = w1s[j * 129 + g * 32 + kk];

    const int r = threadIdx.x >> 6;       // row used during fill/writeback
    for (int base = blockIdx.x * 4; base < BATCH; base += gridDim.x * 4) {
        // fill comb for 4 rows (coalesced 128B per warp)
        {
            const int b = base + r;
            const int node = nodes[b];
            comb[r][j]      = features[(size_t)node * EMBED + j];
            const float inv = 1.0f / fmaxf(g_cnt[b], 1.0f);
            comb[r][64 + j] = g_acc[b * EMBED + j] * inv;
        }
        __syncthreads();

        // each thread: 4 rows x 32-k partial dot products
        #pragma unroll
        for (int rr = 0; rr < 4; ++rr) {
            const float4* c4 = (const float4*)&comb[rr][g * 32];
            float p = 0.0f;
            #pragma unroll
            for (int q = 0; q < 8; ++q) {     // float4 broadcast LDS
                const float4 c = c4[q];
                p = fmaf(c.x, w[q * 4 + 0], p);
                p = fmaf(c.y, w[q * 4 + 1], p);
                p = fmaf(c.z, w[q * 4 + 2], p);
                p = fmaf(c.w, w[q * 4 + 3], p);
            }
            part[rr][j * 5 + g] = p;          // conflict-free (5 coprime 32)
        }
        __syncthreads();

        // reduce 4 partials, bias, relu, store (thread (r, j) owns row r)
        {
            const int b = base + r;
            const float s = part[r][j * 5 + 0] + part[r][j * 5 + 1] +
                            part[r][j * 5 + 2] + part[r][j * 5 + 3] + b1s[j];
            out[(size_t)b * EMBED + j] = fmaxf(s, 0.0f);
        }
        __syncthreads();
    }
}

// ---------------------------------------------------------------------------
// Launch
// inputs: nodes(i32,16384) neigh_ids(i32,524288) seg_ids(i32,524288)
//         features(f32,64M) w1(f32,8192) b1(f32,64)   output: f32 (16384,64)
// ---------------------------------------------------------------------------
extern "C" void kernel_launch(void* const* d_in, const int* in_sizes, int n_in,
                              void* d_out, int out_size) {
    const int*   nodes     = (const int*)  d_in[0];
    const int*   neigh_ids = (const int*)  d_in[1];
    const int*   seg_ids   = (const int*)  d_in[2];
    const float* features  = (const float*)d_in[3];
    const float* w1        = (const float*)d_in[4];
    const float* b1        = (const float*)d_in[5];
    float*       out       = (float*)d_out;

    zero_kernel<<<(262144 + 4096 + 255) / 256, 256>>>();

    const int n_warps  = N_EDGES / 32;            // 16384 warps
    agg_kernel<<<n_warps / 8, 256>>>(neigh_ids, seg_ids, features);

    mlp_kernel<<<512, 256>>>(nodes, features, w1, b1, out);
}